// round 16
// baseline (speedup 1.0000x reference)
#include <cuda_runtime.h>
#include <cuda_fp16.h>
#include <mma.h>
#include <cstdint>

using namespace nvcuda;

#define NPTS 4096
#define NP1  4097
#define PAD  4104           // row stride (elements) for global E arrays
#define NBLK 148            // persistent grid: one block per SM
#define RPB  28             // rows per block (148*28 = 4144 >= 4097)
#define HALF_R 14           // rows per half-batch
#define ITERS_OT 48         // residual(48) ~1e-4 bound from measured flat rel_err at 60/80/100
#define MU_SMALL (1.0f/8192.0f)
#define SCALE_OUT 8192.0f
#define INV_SQRT_D 0.08838834764831845f

// dynamic shared memory layout for sink kernel
#define ESH_BYTES   (RPB * 4096 * 2)            // 229376 B : half E_sh[28][4096]
#define WPART_OFF   ESH_BYTES                   // float wpart[14][32]
#define USH_OFF     (WPART_OFF + HALF_R * 32 * 4)
#define SMEM_SINK   (USH_OFF + RPB * 4)

// dynamic shared memory for gemm kernel: max(As+Bs = 16KB, Cs scratch = 64KB)
#define SMEM_GEMM   (8 * 2048 * 4)              // 65536 B

// ---------------- device scratch ----------------
__device__ float              g_Ef [(size_t)NP1 * PAD];   // fp32 exp(couplings)
__device__ __half             g_Eh [(size_t)NP1 * PAD];   // fp16 copy (row-major)
__device__ float              g_cs[3][PAD];               // triple-buffered colsums
__device__ float              g_U[PAD];
__device__ float              g_V[PAD];
__device__ float              g_ea;                       // exp(bin_score)
__device__ unsigned long long g_rowbest[NPTS];
__device__ unsigned long long g_colbest[NPTS];
__device__ unsigned           g_arrive;
__device__ volatile unsigned  g_release;

// ---------------- PTX helpers ----------------
__device__ __forceinline__ unsigned long long h2_to_f2(unsigned h2) {
    unsigned long long r;
    asm("{\n\t"
        ".reg .b16 lo_h, hi_h;\n\t"
        ".reg .f32 lo_f, hi_f;\n\t"
        "mov.b32 {lo_h, hi_h}, %1;\n\t"
        "cvt.f32.f16 lo_f, lo_h;\n\t"
        "cvt.f32.f16 hi_f, hi_h;\n\t"
        "mov.b64 %0, {lo_f, hi_f};\n\t"
        "}" : "=l"(r) : "r"(h2));
    return r;
}
__device__ __forceinline__ void fma_f32x2(unsigned long long& acc,
                                          unsigned long long a, unsigned long long b) {
    asm("fma.rn.f32x2 %0, %1, %2, %0;" : "+l"(acc) : "l"(a), "l"(b));
}
__device__ __forceinline__ unsigned long long pack_f2(float lo, float hi) {
    unsigned long long r;
    asm("mov.b64 %0, {%1, %2};" : "=l"(r) : "f"(lo), "f"(hi));
    return r;
}
__device__ __forceinline__ void unpack_f2(unsigned long long v, float& lo, float& hi) {
    asm("mov.b64 {%0, %1}, %2;" : "=f"(lo), "=f"(hi) : "l"(v));
}
__device__ __forceinline__ float warp_sum(float v) {
    #pragma unroll
    for (int o = 16; o > 0; o >>= 1) v += __shfl_xor_sync(0xFFFFFFFFu, v, o);
    return v;
}

__device__ __forceinline__ void grid_barrier(int tid, unsigned target) {
    __syncthreads();
    if (tid == 0) {
        __threadfence();
        unsigned prev = atomicAdd(&g_arrive, 1);
        if (prev == (unsigned)(NBLK - 1)) {
            g_arrive = 0;
            __threadfence();
            g_release = target;
        } else {
            while (g_release < target) { __nanosleep(40); }
        }
    }
    __syncthreads();
}

// ---------------- init ----------------
__global__ void init_k(const float* __restrict__ bin) {
    int idx = blockIdx.x * blockDim.x + threadIdx.x;
    float ea = __expf(bin[0]);
    if (idx == 0) { g_arrive = 0; g_release = 0; g_ea = ea; }
    __half eah = __float2half_rn(ea);
    __half zh  = __float2half_rn(0.0f);
    if (idx < PAD) {
        // Iteration k=0 always reads buffer (0+2)%3 == 2: seed with nu so V=1.
        float nu = (idx < NPTS) ? MU_SMALL : (idx == NPTS ? 0.5f : 1.0f);
        g_cs[2][idx] = nu;
        g_cs[0][idx] = 0.0f;   // k=0 write buffer
        g_cs[1][idx] = 0.0f;
    }
    if (idx < NPTS) g_colbest[idx] = 0ull;
    if (idx < NP1) {
        g_Ef[(size_t)idx * PAD + NPTS] = ea;
        g_Eh[(size_t)idx * PAD + NPTS] = eah;
        g_Ef[(size_t)NPTS * PAD + idx] = ea;
        g_Eh[(size_t)NPTS * PAD + idx] = eah;
        #pragma unroll
        for (int p = NP1; p < PAD; p++) {
            g_Ef[(size_t)idx * PAD + p] = 0.0f;
            g_Eh[(size_t)idx * PAD + p] = zh;
        }
    }
}

// ---------------- GEMM (tensor cores, 3xTF32): C = (A^T B)/sqrt(128); E = exp(C) ----
// A = mdesc0 (128 x 4096) row-major; A^T viewed col-major (n x d) with ld=4096.
// B = mdesc1 (128 x 4096) row-major; (d x m) row-major with ld=4096.
// Block tile 128(n) x 128(m); 8 warps as 4(n) x 2(m); warp tile 32 x 64.
// 3xTF32: C = Ahi*Bhi + Ahi*Blo + Alo*Bhi  (fp32-grade accuracy).
__global__ __launch_bounds__(256) void gemm_exp_k(const float* __restrict__ A,
                                                  const float* __restrict__ B) {
    extern __shared__ float smem[];
    float (*As)[128] = (float(*)[128])smem;            // [16][128]  (k-major, n cols)
    float (*Bs)[128] = (float(*)[128])(smem + 2048);   // [16][128]  (k-major, m cols)

    const int tid  = threadIdx.x;
    const int warp = tid >> 5;
    const int lane = tid & 31;
    const int wi   = warp >> 1;       // 0..3  -> n offset 32*wi
    const int wj   = warp & 1;        // 0..1  -> m offset 64*wj
    const int n0   = blockIdx.y * 128;
    const int m0   = blockIdx.x * 128;

    wmma::fragment<wmma::accumulator, 16, 16, 8, float> acc[2][4];
    #pragma unroll
    for (int i = 0; i < 2; i++)
        #pragma unroll
        for (int j = 0; j < 4; j++) wmma::fill_fragment(acc[i][j], 0.0f);

    for (int kk = 0; kk < 128; kk += 16) {
        // stage A,B slabs (same as SIMT version): As[r][c] = A[(kk+r)*4096 + n0+c]
        #pragma unroll
        for (int p = 0; p < 2; p++) {
            int v = tid + p * 256;
            int r = v >> 5;
            int c4 = (v & 31) << 2;
            *(float4*)&As[r][c4] = *(const float4*)&A[(size_t)(kk + r) * 4096 + n0 + c4];
            *(float4*)&Bs[r][c4] = *(const float4*)&B[(size_t)(kk + r) * 4096 + m0 + c4];
        }
        __syncthreads();

        #pragma unroll
        for (int k2 = 0; k2 < 16; k2 += 8) {
            wmma::fragment<wmma::matrix_a, 16, 16, 8, wmma::precision::tf32, wmma::col_major> a_hi[2], a_lo[2];
            wmma::fragment<wmma::matrix_b, 16, 16, 8, wmma::precision::tf32, wmma::row_major> b_hi[4], b_lo[4];
            #pragma unroll
            for (int i = 0; i < 2; i++) {
                wmma::load_matrix_sync(a_hi[i], &As[k2][wi * 32 + i * 16], 128);
                #pragma unroll
                for (int t = 0; t < a_hi[i].num_elements; t++) {
                    float o = a_hi[i].x[t];
                    float h = wmma::__float_to_tf32(o);
                    a_hi[i].x[t] = h;
                    a_lo[i].x[t] = wmma::__float_to_tf32(o - h);
                }
            }
            #pragma unroll
            for (int j = 0; j < 4; j++) {
                wmma::load_matrix_sync(b_hi[j], &Bs[k2][wj * 64 + j * 16], 128);
                #pragma unroll
                for (int t = 0; t < b_hi[j].num_elements; t++) {
                    float o = b_hi[j].x[t];
                    float h = wmma::__float_to_tf32(o);
                    b_hi[j].x[t] = h;
                    b_lo[j].x[t] = wmma::__float_to_tf32(o - h);
                }
            }
            #pragma unroll
            for (int i = 0; i < 2; i++)
                #pragma unroll
                for (int j = 0; j < 4; j++) {
                    wmma::mma_sync(acc[i][j], a_hi[i], b_lo[j], acc[i][j]);
                    wmma::mma_sync(acc[i][j], a_lo[i], b_hi[j], acc[i][j]);
                    wmma::mma_sync(acc[i][j], a_hi[i], b_hi[j], acc[i][j]);
                }
        }
        __syncthreads();
    }

    // epilogue: dump acc frags to per-warp scratch (reuses As/Bs space), exp, write
    float* Cw = smem + warp * 2048;            // 32x64 per warp, ld=64
    #pragma unroll
    for (int i = 0; i < 2; i++)
        #pragma unroll
        for (int j = 0; j < 4; j++)
            wmma::store_matrix_sync(&Cw[(i * 16) * 64 + j * 16], acc[i][j], 64, wmma::mem_row_major);
    __syncwarp();

    for (int idx = lane; idx < 2048; idx += 32) {
        int r = idx >> 6;          // 0..31 (n within warp tile)
        int c = idx & 63;          // 0..63 (m within warp tile)
        int n = n0 + wi * 32 + r;
        int m = m0 + wj * 64 + c;
        float e = __expf(Cw[idx] * INV_SQRT_D);
        g_Ef[(size_t)n * PAD + m] = e;
        g_Eh[(size_t)n * PAD + m] = __float2half_rn(e);
    }
}

// ---------------- persistent Sinkhorn: E in SMEM, flat 2-pass ----------------
__global__ __launch_bounds__(1024, 1) void sink_smem_k() {
    extern __shared__ char smem_raw[];
    __half* E_sh  = (__half*)smem_raw;                     // [28][4096]
    float*  wpart = (float*)(smem_raw + WPART_OFF);        // [14][32]
    float*  u_sh  = (float*)(smem_raw + USH_OFF);          // [28]

    const int tid  = threadIdx.x;
    const int warp = tid >> 5;
    const int lane = tid & 31;
    const int bid  = blockIdx.x;
    const int r0   = bid * RPB;
    const int col0 = tid * 4;                 // owned columns (all < 4096)
    const float ea = g_ea;

    // ---- one-time: stage this block's 28-row E slice into SMEM ----
    #pragma unroll
    for (int q = 0; q < RPB; q++) {
        int gr = r0 + q; if (gr > NPTS) gr = NPTS;         // clamp (u forced 0 later)
        uint2 v = *(const uint2*)(g_Eh + (size_t)gr * PAD + col0);
        *(uint2*)((char*)E_sh + (size_t)q * 8192 + tid * 8) = v;
    }
    __syncthreads();

    for (int k = 0; k < ITERS_OT; k++) {
        const int R = (k + 2) % 3;            // read buffer (prev colsums)
        const int W = k % 3;                  // write buffer (this iter's colsums)
        const int C = (k + 1) % 3;            // clear for next iter (race-free)

        if (tid < RPB) {
            int c = r0 + tid;
            if (c < PAD) g_cs[C][c] = 0.0f;
        }

        // per-thread V for owned columns + bin V
        float4 cv = __ldcg((const float4*)&g_cs[R][col0]);
        const unsigned long long V01 = pack_f2(__fdividef(MU_SMALL, cv.x),
                                               __fdividef(MU_SMALL, cv.y));
        const unsigned long long V23 = pack_f2(__fdividef(MU_SMALL, cv.z),
                                               __fdividef(MU_SMALL, cv.w));
        const float vbin = __fdividef(0.5f, __ldcg(&g_cs[R][NPTS]));
        const float eavb = ea * vbin;

        // ---- dot pass: two half-batches of 14 rows ----
        #pragma unroll
        for (int h = 0; h < 2; h++) {
            const int base = h * HALF_R;
            float p[HALF_R];
            #pragma unroll
            for (int q = 0; q < HALF_R; q++) {
                uint2 e = *(const uint2*)((char*)E_sh + (size_t)(base + q) * 8192 + tid * 8);
                unsigned long long acc = 0ull;
                fma_f32x2(acc, h2_to_f2(e.x), V01);
                fma_f32x2(acc, h2_to_f2(e.y), V23);
                float lo, hi; unpack_f2(acc, lo, hi);
                p[q] = lo + hi;
            }
            #pragma unroll
            for (int o = 16; o > 0; o >>= 1)
                #pragma unroll
                for (int q = 0; q < HALF_R; q++)
                    p[q] += __shfl_xor_sync(0xFFFFFFFFu, p[q], o);
            if (lane == 0) {
                #pragma unroll
                for (int q = 0; q < HALF_R; q++) wpart[q * 32 + warp] = p[q];
            }
            __syncthreads();

            if (warp < HALF_R) {
                float v = warp_sum(wpart[warp * 32 + lane]);
                if (lane == 0) {
                    int row = r0 + base + warp;
                    float dot = v + eavb;
                    float mu = (row < NPTS) ? MU_SMALL : (row == NPTS ? 0.5f : 0.0f);
                    float u = __fdividef(mu, dot);
                    u_sh[base + warp] = u;
                    if (k == ITERS_OT - 1 && row < NP1) g_U[row] = u;
                }
            }
            __syncthreads();   // also guards wpart reuse by next half
        }

        // ---- colsum pass (packed FMA; u broadcast from SMEM) ----
        unsigned long long cs01 = 0ull, cs23 = 0ull;
        #pragma unroll
        for (int q = 0; q < RPB; q++) {
            float uq = u_sh[q];
            unsigned long long u2 = pack_f2(uq, uq);
            uint2 e = *(const uint2*)((char*)E_sh + (size_t)q * 8192 + tid * 8);
            fma_f32x2(cs01, h2_to_f2(e.x), u2);
            fma_f32x2(cs23, h2_to_f2(e.y), u2);
        }
        float c0, c1, c2, c3;
        unpack_f2(cs01, c0, c1);
        unpack_f2(cs23, c2, c3);
        float* cs = g_cs[W];
        atomicAdd((float4*)&cs[col0], make_float4(c0, c1, c2, c3));
        if (warp == 0) {
            float uu = (lane < RPB) ? u_sh[lane] : 0.0f;
            uu = warp_sum(uu);
            if (lane == 0) atomicAdd(&cs[NPTS], ea * uu);
        }

        grid_barrier(tid, (unsigned)(k + 1));
    }
}

// ---------------- finalize V from last colsum buffer ----------------
__global__ void finalize_v_k() {
    int idx = blockIdx.x * blockDim.x + threadIdx.x;
    if (idx < PAD) {
        if (idx < NP1) {
            float nu = (idx < NPTS) ? MU_SMALL : 0.5f;
            g_V[idx] = nu / g_cs[(ITERS_OT - 1) % 3][idx];   // == last iter's W buffer
        } else {
            g_V[idx] = 0.0f;
        }
    }
}

// ---------------- epilogue: P = Ef*U*V*8192 -> out; row max/argmax ----------------
__global__ __launch_bounds__(256) void epilogue_k(float* __restrict__ out) {
    int i = blockIdx.x;
    int t = threadIdx.x;
    float Ui = g_U[i] * SCALE_OUT;
    unsigned long long best = 0ull;
    for (int j = t; j < NP1; j += 256) {
        float p = g_Ef[(size_t)i * PAD + j] * Ui * g_V[j];
        out[(size_t)i * NP1 + j] = p;
        if (j < NPTS) {
            unsigned long long pk =
                ((unsigned long long)__float_as_uint(p) << 32) | (unsigned)(4095 - j);
            best = (pk > best) ? pk : best;
        }
    }
    __shared__ unsigned long long sb[256];
    sb[t] = best;
    __syncthreads();
    #pragma unroll
    for (int s = 128; s > 0; s >>= 1) {
        if (t < s) { if (sb[t + s] > sb[t]) sb[t] = sb[t + s]; }
        __syncthreads();
    }
    if (t == 0 && i < NPTS) g_rowbest[i] = sb[0];
}

// ---------------- column max/argmax ----------------
__global__ __launch_bounds__(256) void colmax_k(const float* __restrict__ out) {
    int c  = blockIdx.x * 256 + threadIdx.x;
    int i0 = blockIdx.y * 128;
    unsigned long long best = 0ull;
    #pragma unroll 4
    for (int r = 0; r < 128; r++) {
        int i = i0 + r;
        float p = out[(size_t)i * NP1 + c];
        unsigned long long pk =
            ((unsigned long long)__float_as_uint(p) << 32) | (unsigned)(4095 - i);
        best = (pk > best) ? pk : best;
    }
    atomicMax(&g_colbest[c], best);
}

// ---------------- final matching outputs ----------------
__global__ __launch_bounds__(256) void final_k(float* __restrict__ out) {
    int idx = blockIdx.x * 256 + threadIdx.x;
    if (idx >= NPTS) return;
    size_t base = (size_t)NP1 * NP1;

    unsigned long long rb = g_rowbest[idx];
    int   j0   = 4095 - (int)(unsigned)(rb & 0xFFFFFFFFull);
    float maxP = __uint_as_float((unsigned)(rb >> 32));
    unsigned long long cbj = g_colbest[j0];
    int   iback = 4095 - (int)(unsigned)(cbj & 0xFFFFFFFFull);
    bool  mutual0 = (iback == idx);
    float ms0 = mutual0 ? maxP : 0.0f;
    bool  valid0 = mutual0 && (ms0 > 0.2f);
    float idx0f = valid0 ? (float)j0 : -1.0f;

    unsigned long long cb = g_colbest[idx];
    int   i0 = 4095 - (int)(unsigned)(cb & 0xFFFFFFFFull);
    unsigned long long rbi = g_rowbest[i0];
    int   jback = 4095 - (int)(unsigned)(rbi & 0xFFFFFFFFull);
    float rmax  = __uint_as_float((unsigned)(rbi >> 32));
    bool  mutual1 = (jback == idx);
    float ms1 = mutual1 ? rmax : 0.0f;
    bool  valid1 = mutual1 && (rmax > 0.2f);
    float idx1f = valid1 ? (float)i0 : -1.0f;

    out[base + idx]          = idx0f;
    out[base + 4096 + idx]   = idx1f;
    out[base + 8192 + idx]   = ms0;
    out[base + 12288 + idx]  = ms1;
}

// ---------------- launch ----------------
extern "C" void kernel_launch(void* const* d_in, const int* in_sizes, int n_in,
                              void* d_out, int out_size) {
    const float* A   = (const float*)d_in[0];   // mdesc0 (1,128,4096)
    const float* B   = (const float*)d_in[1];   // mdesc1 (1,128,4096)
    const float* bin = (const float*)d_in[2];   // bin_score scalar
    float* out = (float*)d_out;

    cudaFuncSetAttribute(sink_smem_k,
                         cudaFuncAttributeMaxDynamicSharedMemorySize, SMEM_SINK);
    cudaFuncSetAttribute(gemm_exp_k,
                         cudaFuncAttributeMaxDynamicSharedMemorySize, SMEM_GEMM);

    init_k<<<17, 256>>>(bin);
    gemm_exp_k<<<dim3(32, 32), 256, SMEM_GEMM>>>(A, B);
    sink_smem_k<<<NBLK, 1024, SMEM_SINK>>>();   // 48 iterations, one launch

    finalize_v_k<<<17, 256>>>();
    epilogue_k<<<NP1, 256>>>(out);
    colmax_k<<<dim3(16, 32), 256>>>(out);
    final_k<<<16, 256>>>(out);
}

// round 17
// speedup vs baseline: 1.4490x; 1.4490x over previous
#include <cuda_runtime.h>
#include <cuda_fp16.h>
#include <cstdint>

#define NPTS 4096
#define NP1  4097
#define PAD  4104           // row stride (elements) for global E arrays
#define NBLK 148            // persistent grid: one block per SM
#define RPB  28             // rows per block (148*28 = 4144 >= 4097)
#define HALF_R 14           // rows per half-batch
#define ITERS_OT 48         // validated R16: rel_err 5.2e-5, flat vs 60/80/100
#define MU_SMALL (1.0f/8192.0f)
#define SCALE_OUT 8192.0f
#define INV_SQRT_D 0.08838834764831845f

// dynamic shared memory layout for sink kernel
#define ESH_BYTES   (RPB * 4096 * 2)            // 229376 B : half E_sh[28][4096]
#define WPART_OFF   ESH_BYTES                   // float wpart[14][32]
#define USH_OFF     (WPART_OFF + HALF_R * 32 * 4)
#define SMEM_SINK   (USH_OFF + RPB * 4)

// ---------------- device scratch ----------------
__device__ float              g_Ef [(size_t)NP1 * PAD];   // fp32 exp(couplings)
__device__ __half             g_Eh [(size_t)NP1 * PAD];   // fp16 copy (row-major)
__device__ float              g_cs[3][PAD];               // triple-buffered colsums
__device__ float              g_U[PAD];
__device__ float              g_V[PAD];
__device__ float              g_ea;                       // exp(bin_score)
__device__ unsigned long long g_rowbest[NPTS];
__device__ unsigned long long g_colbest[NPTS];
__device__ unsigned           g_arrive;
__device__ volatile unsigned  g_release;

// ---------------- PTX helpers ----------------
__device__ __forceinline__ unsigned long long h2_to_f2(unsigned h2) {
    unsigned long long r;
    asm("{\n\t"
        ".reg .b16 lo_h, hi_h;\n\t"
        ".reg .f32 lo_f, hi_f;\n\t"
        "mov.b32 {lo_h, hi_h}, %1;\n\t"
        "cvt.f32.f16 lo_f, lo_h;\n\t"
        "cvt.f32.f16 hi_f, hi_h;\n\t"
        "mov.b64 %0, {lo_f, hi_f};\n\t"
        "}" : "=l"(r) : "r"(h2));
    return r;
}
__device__ __forceinline__ void fma_f32x2(unsigned long long& acc,
                                          unsigned long long a, unsigned long long b) {
    asm("fma.rn.f32x2 %0, %1, %2, %0;" : "+l"(acc) : "l"(a), "l"(b));
}
__device__ __forceinline__ unsigned long long pack_f2(float lo, float hi) {
    unsigned long long r;
    asm("mov.b64 %0, {%1, %2};" : "=l"(r) : "f"(lo), "f"(hi));
    return r;
}
__device__ __forceinline__ void unpack_f2(unsigned long long v, float& lo, float& hi) {
    asm("mov.b64 {%0, %1}, %2;" : "=f"(lo), "=f"(hi) : "l"(v));
}
__device__ __forceinline__ float warp_sum(float v) {
    #pragma unroll
    for (int o = 16; o > 0; o >>= 1) v += __shfl_xor_sync(0xFFFFFFFFu, v, o);
    return v;
}

__device__ __forceinline__ void grid_barrier(int tid, unsigned target) {
    __syncthreads();
    if (tid == 0) {
        __threadfence();
        unsigned prev = atomicAdd(&g_arrive, 1);
        if (prev == (unsigned)(NBLK - 1)) {
            g_arrive = 0;
            __threadfence();
            g_release = target;
        } else {
            while (g_release < target) { __nanosleep(40); }
        }
    }
    __syncthreads();
}

// ---------------- init ----------------
__global__ void init_k(const float* __restrict__ bin) {
    int idx = blockIdx.x * blockDim.x + threadIdx.x;
    float ea = __expf(bin[0]);
    if (idx == 0) { g_arrive = 0; g_release = 0; g_ea = ea; }
    __half eah = __float2half_rn(ea);
    __half zh  = __float2half_rn(0.0f);
    if (idx < PAD) {
        // Iteration k=0 always reads buffer (0+2)%3 == 2: seed with nu so V=1.
        float nu = (idx < NPTS) ? MU_SMALL : (idx == NPTS ? 0.5f : 1.0f);
        g_cs[2][idx] = nu;
        g_cs[0][idx] = 0.0f;   // k=0 write buffer
        g_cs[1][idx] = 0.0f;
    }
    if (idx < NPTS) g_colbest[idx] = 0ull;
    if (idx < NP1) {
        g_Ef[(size_t)idx * PAD + NPTS] = ea;
        g_Eh[(size_t)idx * PAD + NPTS] = eah;
        g_Ef[(size_t)NPTS * PAD + idx] = ea;
        g_Eh[(size_t)NPTS * PAD + idx] = eah;
        #pragma unroll
        for (int p = NP1; p < PAD; p++) {
            g_Ef[(size_t)idx * PAD + p] = 0.0f;
            g_Eh[(size_t)idx * PAD + p] = zh;
        }
    }
}

// ---------------- GEMM (SIMT fp32, R15-proven): C = (A^T B)/sqrt(128); E = exp(C) ----
__global__ __launch_bounds__(256) void gemm_exp_k(const float* __restrict__ A,
                                                  const float* __restrict__ B) {
    __shared__ float As[16][128];
    __shared__ float Bs[16][128];
    int tid = threadIdx.x;
    int tx = tid & 15;
    int ty = tid >> 4;
    int n0 = blockIdx.y * 128;
    int m0 = blockIdx.x * 128;

    float acc[8][8];
    #pragma unroll
    for (int i = 0; i < 8; i++)
        #pragma unroll
        for (int j = 0; j < 8; j++) acc[i][j] = 0.0f;

    for (int kk = 0; kk < 128; kk += 16) {
        #pragma unroll
        for (int p = 0; p < 2; p++) {
            int v = tid + p * 256;
            int r = v >> 5;
            int c4 = (v & 31) << 2;
            *(float4*)&As[r][c4] = *(const float4*)&A[(size_t)(kk + r) * 4096 + n0 + c4];
            *(float4*)&Bs[r][c4] = *(const float4*)&B[(size_t)(kk + r) * 4096 + m0 + c4];
        }
        __syncthreads();
        #pragma unroll
        for (int k = 0; k < 16; k++) {
            float a[8], b[8];
            *(float4*)&a[0] = *(float4*)&As[k][ty * 8];
            *(float4*)&a[4] = *(float4*)&As[k][ty * 8 + 4];
            *(float4*)&b[0] = *(float4*)&Bs[k][tx * 8];
            *(float4*)&b[4] = *(float4*)&Bs[k][tx * 8 + 4];
            #pragma unroll
            for (int i = 0; i < 8; i++)
                #pragma unroll
                for (int j = 0; j < 8; j++)
                    acc[i][j] = fmaf(a[i], b[j], acc[i][j]);
        }
        __syncthreads();
    }

    #pragma unroll
    for (int i = 0; i < 8; i++) {
        int n = n0 + ty * 8 + i;
        #pragma unroll
        for (int j = 0; j < 8; j++) {
            int m = m0 + tx * 8 + j;
            float e = __expf(acc[i][j] * INV_SQRT_D);
            g_Ef[(size_t)n * PAD + m] = e;
            g_Eh[(size_t)n * PAD + m] = __float2half_rn(e);
        }
    }
}

// ---------------- persistent Sinkhorn: E in SMEM, flat 2-pass, fused V-finalize ----
__global__ __launch_bounds__(1024, 1) void sink_smem_k() {
    extern __shared__ char smem_raw[];
    __half* E_sh  = (__half*)smem_raw;                     // [28][4096]
    float*  wpart = (float*)(smem_raw + WPART_OFF);        // [14][32]
    float*  u_sh  = (float*)(smem_raw + USH_OFF);          // [28]

    const int tid  = threadIdx.x;
    const int warp = tid >> 5;
    const int lane = tid & 31;
    const int bid  = blockIdx.x;
    const int r0   = bid * RPB;
    const int col0 = tid * 4;                 // owned columns (all < 4096)
    const float ea = g_ea;

    // ---- one-time: stage this block's 28-row E slice into SMEM ----
    #pragma unroll
    for (int q = 0; q < RPB; q++) {
        int gr = r0 + q; if (gr > NPTS) gr = NPTS;         // clamp (u forced 0 later)
        uint2 v = *(const uint2*)(g_Eh + (size_t)gr * PAD + col0);
        *(uint2*)((char*)E_sh + (size_t)q * 8192 + tid * 8) = v;
    }
    __syncthreads();

    for (int k = 0; k < ITERS_OT; k++) {
        const int R = (k + 2) % 3;            // read buffer (prev colsums)
        const int W = k % 3;                  // write buffer (this iter's colsums)
        const int C = (k + 1) % 3;            // clear for next iter (race-free)

        if (tid < RPB) {
            int c = r0 + tid;
            if (c < PAD) g_cs[C][c] = 0.0f;
        }

        // per-thread V for owned columns + bin V
        float4 cv = __ldcg((const float4*)&g_cs[R][col0]);
        const unsigned long long V01 = pack_f2(__fdividef(MU_SMALL, cv.x),
                                               __fdividef(MU_SMALL, cv.y));
        const unsigned long long V23 = pack_f2(__fdividef(MU_SMALL, cv.z),
                                               __fdividef(MU_SMALL, cv.w));
        const float vbin = __fdividef(0.5f, __ldcg(&g_cs[R][NPTS]));
        const float eavb = ea * vbin;

        // ---- dot pass: two half-batches of 14 rows ----
        #pragma unroll
        for (int h = 0; h < 2; h++) {
            const int base = h * HALF_R;
            float p[HALF_R];
            #pragma unroll
            for (int q = 0; q < HALF_R; q++) {
                uint2 e = *(const uint2*)((char*)E_sh + (size_t)(base + q) * 8192 + tid * 8);
                unsigned long long acc = 0ull;
                fma_f32x2(acc, h2_to_f2(e.x), V01);
                fma_f32x2(acc, h2_to_f2(e.y), V23);
                float lo, hi; unpack_f2(acc, lo, hi);
                p[q] = lo + hi;
            }
            #pragma unroll
            for (int o = 16; o > 0; o >>= 1)
                #pragma unroll
                for (int q = 0; q < HALF_R; q++)
                    p[q] += __shfl_xor_sync(0xFFFFFFFFu, p[q], o);
            if (lane == 0) {
                #pragma unroll
                for (int q = 0; q < HALF_R; q++) wpart[q * 32 + warp] = p[q];
            }
            __syncthreads();

            if (warp < HALF_R) {
                float v = warp_sum(wpart[warp * 32 + lane]);
                if (lane == 0) {
                    int row = r0 + base + warp;
                    float dot = v + eavb;
                    float mu = (row < NPTS) ? MU_SMALL : (row == NPTS ? 0.5f : 0.0f);
                    float u = __fdividef(mu, dot);
                    u_sh[base + warp] = u;
                    if (k == ITERS_OT - 1 && row < NP1) g_U[row] = u;
                }
            }
            __syncthreads();   // also guards wpart reuse by next half
        }

        // ---- colsum pass (packed FMA; u broadcast from SMEM) ----
        unsigned long long cs01 = 0ull, cs23 = 0ull;
        #pragma unroll
        for (int q = 0; q < RPB; q++) {
            float uq = u_sh[q];
            unsigned long long u2 = pack_f2(uq, uq);
            uint2 e = *(const uint2*)((char*)E_sh + (size_t)q * 8192 + tid * 8);
            fma_f32x2(cs01, h2_to_f2(e.x), u2);
            fma_f32x2(cs23, h2_to_f2(e.y), u2);
        }
        float c0, c1, c2, c3;
        unpack_f2(cs01, c0, c1);
        unpack_f2(cs23, c2, c3);
        float* cs = g_cs[W];
        atomicAdd((float4*)&cs[col0], make_float4(c0, c1, c2, c3));
        if (warp == 0) {
            float uu = (lane < RPB) ? u_sh[lane] : 0.0f;
            uu = warp_sum(uu);
            if (lane == 0) atomicAdd(&cs[NPTS], ea * uu);
        }

        grid_barrier(tid, (unsigned)(k + 1));
    }

    // ---- fused V finalize: last iter's colsums (buffer (ITERS-1)%3) are all
    // visible after the final grid barrier. Each block finalizes its own slab.
    if (tid < RPB) {
        int c = r0 + tid;
        if (c < NP1) {
            float nu = (c < NPTS) ? MU_SMALL : 0.5f;
            g_V[c] = __fdividef(nu, __ldcg(&g_cs[(ITERS_OT - 1) % 3][c]));
        }
    }
    // pad region of g_V is never read by epilogue (j < NP1 loop) — no init needed.
}

// ---------------- epilogue: P = Ef*U*V*8192 -> out; row max/argmax ----------------
__global__ __launch_bounds__(256) void epilogue_k(float* __restrict__ out) {
    int i = blockIdx.x;
    int t = threadIdx.x;
    float Ui = g_U[i] * SCALE_OUT;
    unsigned long long best = 0ull;
    for (int j = t; j < NP1; j += 256) {
        float p = g_Ef[(size_t)i * PAD + j] * Ui * g_V[j];
        out[(size_t)i * NP1 + j] = p;
        if (j < NPTS) {
            unsigned long long pk =
                ((unsigned long long)__float_as_uint(p) << 32) | (unsigned)(4095 - j);
            best = (pk > best) ? pk : best;
        }
    }
    __shared__ unsigned long long sb[256];
    sb[t] = best;
    __syncthreads();
    #pragma unroll
    for (int s = 128; s > 0; s >>= 1) {
        if (t < s) { if (sb[t + s] > sb[t]) sb[t] = sb[t + s]; }
        __syncthreads();
    }
    if (t == 0 && i < NPTS) g_rowbest[i] = sb[0];
}

// ---------------- column max/argmax ----------------
__global__ __launch_bounds__(256) void colmax_k(const float* __restrict__ out) {
    int c  = blockIdx.x * 256 + threadIdx.x;
    int i0 = blockIdx.y * 128;
    unsigned long long best = 0ull;
    #pragma unroll 4
    for (int r = 0; r < 128; r++) {
        int i = i0 + r;
        float p = out[(size_t)i * NP1 + c];
        unsigned long long pk =
            ((unsigned long long)__float_as_uint(p) << 32) | (unsigned)(4095 - i);
        best = (pk > best) ? pk : best;
    }
    atomicMax(&g_colbest[c], best);
}

// ---------------- final matching outputs ----------------
__global__ __launch_bounds__(256) void final_k(float* __restrict__ out) {
    int idx = blockIdx.x * 256 + threadIdx.x;
    if (idx >= NPTS) return;
    size_t base = (size_t)NP1 * NP1;

    unsigned long long rb = g_rowbest[idx];
    int   j0   = 4095 - (int)(unsigned)(rb & 0xFFFFFFFFull);
    float maxP = __uint_as_float((unsigned)(rb >> 32));
    unsigned long long cbj = g_colbest[j0];
    int   iback = 4095 - (int)(unsigned)(cbj & 0xFFFFFFFFull);
    bool  mutual0 = (iback == idx);
    float ms0 = mutual0 ? maxP : 0.0f;
    bool  valid0 = mutual0 && (ms0 > 0.2f);
    float idx0f = valid0 ? (float)j0 : -1.0f;

    unsigned long long cb = g_colbest[idx];
    int   i0 = 4095 - (int)(unsigned)(cb & 0xFFFFFFFFull);
    unsigned long long rbi = g_rowbest[i0];
    int   jback = 4095 - (int)(unsigned)(rbi & 0xFFFFFFFFull);
    float rmax  = __uint_as_float((unsigned)(rbi >> 32));
    bool  mutual1 = (jback == idx);
    float ms1 = mutual1 ? rmax : 0.0f;
    bool  valid1 = mutual1 && (rmax > 0.2f);
    float idx1f = valid1 ? (float)i0 : -1.0f;

    out[base + idx]          = idx0f;
    out[base + 4096 + idx]   = idx1f;
    out[base + 8192 + idx]   = ms0;
    out[base + 12288 + idx]  = ms1;
}

// ---------------- launch ----------------
extern "C" void kernel_launch(void* const* d_in, const int* in_sizes, int n_in,
                              void* d_out, int out_size) {
    const float* A   = (const float*)d_in[0];   // mdesc0 (1,128,4096)
    const float* B   = (const float*)d_in[1];   // mdesc1 (1,128,4096)
    const float* bin = (const float*)d_in[2];   // bin_score scalar
    float* out = (float*)d_out;

    cudaFuncSetAttribute(sink_smem_k,
                         cudaFuncAttributeMaxDynamicSharedMemorySize, SMEM_SINK);

    init_k<<<17, 256>>>(bin);                   // idx 0
    gemm_exp_k<<<dim3(32, 32), 256>>>(A, B);    // idx 1
    sink_smem_k<<<NBLK, 1024, SMEM_SINK>>>();   // idx 2 (48 iters + fused V finalize)
    epilogue_k<<<NP1, 256>>>(out);              // idx 3 <- ncu capture slot
    colmax_k<<<dim3(16, 32), 256>>>(out);
    final_k<<<16, 256>>>(out);
}